// round 2
// baseline (speedup 1.0000x reference)
#include <cuda_runtime.h>

#define THREADS 128
#define SB 8           // samples per CTA
#define NQ 7           // quantities per neuron: h, J0..2, T0..2
#define DH 256         // hidden width

// ---- packed f32x2 helpers (Blackwell FFMA2: 2 fp32 FMAs per instruction) ----
__device__ __forceinline__ unsigned long long bc2(float a) {
    unsigned long long r;
    asm("mov.b64 %0, {%1, %1};" : "=l"(r) : "f"(a));
    return r;
}
__device__ __forceinline__ void fma2(unsigned long long& d, unsigned long long a,
                                     unsigned long long b) {
    asm("fma.rn.f32x2 %0, %1, %2, %0;" : "+l"(d) : "l"(a), "l"(b));
}
__device__ __forceinline__ void up2(unsigned long long v, float& lo, float& hi) {
    asm("mov.b64 {%0, %1}, %2;" : "=f"(lo), "=f"(hi) : "l"(v));
}

// State layout in dynamic smem: S[q][i][s], q in [0,7), i in [0,256), s in [0,8)
#define SIDX(q, i, s) (((q) * DH + (i)) * SB + (s))

__global__ void __launch_bounds__(THREADS) pinn_fwd2_kernel(
    const float* __restrict__ x,
    const float* __restrict__ W0, const float* __restrict__ b0,
    const float* __restrict__ W1, const float* __restrict__ b1,
    const float* __restrict__ W2, const float* __restrict__ b2,
    const float* __restrict__ W3, const float* __restrict__ b3,
    const float* __restrict__ W4, const float* __restrict__ b4,
    const float* __restrict__ lb, const float* __restrict__ ub,
    float* __restrict__ out, int N)
{
    extern __shared__ float S[];          // NQ*DH*SB floats = 57344 B
    __shared__ float w4s[DH * 2];
    __shared__ float b4s[2];

    const int tid = threadIdx.x;
    const int s0  = blockIdx.x * SB;

    // Stage final-layer weights (consumed after last barrier).
    for (int i = tid; i < DH * 2; i += THREADS) w4s[i] = W4[i];
    if (tid < 2) b4s[tid] = b4[tid];

    // Input normalization constants
    float lbv[3], sk[3];
#pragma unroll
    for (int k = 0; k < 3; k++) {
        lbv[k] = lb[k];
        sk[k]  = 2.0f / (ub[k] - lb[k]);
    }

    // Normalized inputs for this CTA's samples
    float H[SB][3];
#pragma unroll
    for (int s = 0; s < SB; s++)
#pragma unroll
        for (int k = 0; k < 3; k++)
            H[s][k] = sk[k] * (x[(s0 + s) * 3 + k] - lbv[k]) - 1.0f;

    // ---------------- Layer 0: 3 -> 256 ----------------
    // dH0[i]/dx_k = sk[k] * delta_ik ; T input = 0
#pragma unroll
    for (int nn = 0; nn < 2; nn++) {
        const int j = tid + nn * THREADS;
        float w[3];
#pragma unroll
        for (int k = 0; k < 3; k++) w[k] = W0[k * DH + j];
        const float bj = b0[j];
        float zj[3], Szl = 0.0f;
#pragma unroll
        for (int k = 0; k < 3; k++) { zj[k] = w[k] * sk[k]; Szl += zj[k]; }
#pragma unroll
        for (int s = 0; s < SB; s++) {
            float z = bj + w[0] * H[s][0] + w[1] * H[s][1] + w[2] * H[s][2];
            float t = tanhf(z);
            float g = 1.0f - t * t;
            float u = -2.0f * t * g * Szl;
            S[SIDX(0, j, s)] = t;
#pragma unroll
            for (int k = 0; k < 3; k++) {
                S[SIDX(1 + k, j, s)] = g * zj[k];
                S[SIDX(4 + k, j, s)] = u * zj[k];
            }
        }
    }
    __syncthreads();

    // ---------------- Hidden layers 1..3: 256 -> 256 ----------------
    for (int L = 0; L < 3; L++) {
        const float* __restrict__ W = (L == 0) ? W1 : ((L == 1) ? W2 : W3);
        const float* __restrict__ b = (L == 0) ? b1 : ((L == 1) ? b2 : b3);

        unsigned long long acc[2][NQ][4];
#pragma unroll
        for (int nn = 0; nn < 2; nn++) {
            unsigned long long bb = bc2(b[tid + nn * THREADS]);
#pragma unroll
            for (int p = 0; p < 4; p++) acc[nn][0][p] = bb;
#pragma unroll
            for (int q = 1; q < NQ; q++)
#pragma unroll
                for (int p = 0; p < 4; p++) acc[nn][q][p] = 0ull;
        }

        const int j0 = tid, j1 = tid + THREADS;
#pragma unroll 4
        for (int i = 0; i < DH; i++) {
            unsigned long long w0 = bc2(W[i * DH + j0]);
            unsigned long long w1 = bc2(W[i * DH + j1]);
#pragma unroll
            for (int q = 0; q < NQ; q++) {
                const ulonglong2* p =
                    reinterpret_cast<const ulonglong2*>(&S[SIDX(q, i, 0)]);
                ulonglong2 v0 = p[0];
                ulonglong2 v1 = p[1];
                fma2(acc[0][q][0], w0, v0.x);
                fma2(acc[0][q][1], w0, v0.y);
                fma2(acc[0][q][2], w0, v1.x);
                fma2(acc[0][q][3], w0, v1.y);
                fma2(acc[1][q][0], w1, v0.x);
                fma2(acc[1][q][1], w1, v0.y);
                fma2(acc[1][q][2], w1, v1.x);
                fma2(acc[1][q][3], w1, v1.y);
            }
        }
        __syncthreads();   // everyone done reading old state

#pragma unroll
        for (int nn = 0; nn < 2; nn++) {
            const int j = tid + nn * THREADS;
#pragma unroll
            for (int p = 0; p < 4; p++) {
                float zh[2], zj0[2], zj1[2], zj2[2], zt0[2], zt1[2], zt2[2];
                up2(acc[nn][0][p], zh[0], zh[1]);
                up2(acc[nn][1][p], zj0[0], zj0[1]);
                up2(acc[nn][2][p], zj1[0], zj1[1]);
                up2(acc[nn][3][p], zj2[0], zj2[1]);
                up2(acc[nn][4][p], zt0[0], zt0[1]);
                up2(acc[nn][5][p], zt1[0], zt1[1]);
                up2(acc[nn][6][p], zt2[0], zt2[1]);
#pragma unroll
                for (int e = 0; e < 2; e++) {
                    const int s = p * 2 + e;
                    float t  = tanhf(zh[e]);
                    float g  = 1.0f - t * t;
                    float Sz = zj0[e] + zj1[e] + zj2[e];
                    float u  = -2.0f * t * g * Sz;
                    S[SIDX(0, j, s)] = t;
                    S[SIDX(1, j, s)] = g * zj0[e];
                    S[SIDX(2, j, s)] = g * zj1[e];
                    S[SIDX(3, j, s)] = g * zj2[e];
                    S[SIDX(4, j, s)] = u * zj0[e] + g * zt0[e];
                    S[SIDX(5, j, s)] = u * zj1[e] + g * zt1[e];
                    S[SIDX(6, j, s)] = u * zj2[e] + g * zt2[e];
                }
            }
        }
        __syncthreads();   // new state visible for next layer
    }

    // ---------------- Final layer: 256 -> 2 (linear) ----------------
    // 7 quantities x 2 outputs x 8 samples = 112 dot products of length 256.
    if (tid < NQ * 2 * SB) {
        const int q = tid % NQ;
        const int o = (tid / NQ) & 1;
        const int s = tid / (NQ * 2);
        float sum = 0.0f;
#pragma unroll 8
        for (int i = 0; i < DH; i++)
            sum += w4s[i * 2 + o] * S[SIDX(q, i, s)];
        const int n = s0 + s;
        if (q == 0) {
            out[n * 2 + o] = sum + b4s[o];                    // out[N,2]
        } else if (q < 4) {
            out[2 * N + o * 3 * N + n * 3 + (q - 1)] = sum;   // partials_1[2,N,3]
        } else {
            out[8 * N + o * 3 * N + n * 3 + (q - 4)] = sum;   // partials_2[2,N,3]
        }
    }
}

extern "C" void kernel_launch(void* const* d_in, const int* in_sizes, int n_in,
                              void* d_out, int out_size)
{
    const float* x  = (const float*)d_in[0];
    const float* W0 = (const float*)d_in[1];
    const float* b0 = (const float*)d_in[2];
    const float* W1 = (const float*)d_in[3];
    const float* b1 = (const float*)d_in[4];
    const float* W2 = (const float*)d_in[5];
    const float* b2 = (const float*)d_in[6];
    const float* W3 = (const float*)d_in[7];
    const float* b3 = (const float*)d_in[8];
    const float* W4 = (const float*)d_in[9];
    const float* b4 = (const float*)d_in[10];
    const float* lb = (const float*)d_in[11];
    const float* ub = (const float*)d_in[12];
    float* out = (float*)d_out;

    const int N = in_sizes[0] / 3;          // 32768
    const int smem = NQ * DH * SB * (int)sizeof(float);   // 57344 B

    cudaFuncSetAttribute(pinn_fwd2_kernel,
                         cudaFuncAttributeMaxDynamicSharedMemorySize, smem);

    pinn_fwd2_kernel<<<N / SB, THREADS, smem>>>(
        x, W0, b0, W1, b1, W2, b2, W3, b3, W4, b4, lb, ub, out, N);
}